// round 17
// baseline (speedup 1.0000x reference)
#include <cuda_runtime.h>
#include <cuda_bf16.h>

// S4D layer: B=8, H=128, N=64, L=8192.
// y[b,h,l] = Re( sum_n g_n * s_n[l] ) + D[h]*x[b,h,l]
// s_n[l] = w_n * s_n[l-1] + x[b,h,l],  s_n[-1] = 0
//
// One warp per (b,h) row; 2 complex modes per lane packed into f32x2 vectors.
// 2-step blocked recurrence (z <- w^2 z + w x1 + x2) to shorten the dependent
// chain to 2 FFMA2 per 2 steps; outputs emitted from the held state
// (y_even = Re(g z), y_odd = Re(gw z) + Re(g) x1) so they are off the chain.
// Per-step partials stay packed (f32x2) through the 31-shuffle transpose-fold;
// a single unpack+add per 32 steps lands y[l0+lane] in lane `lane` for one
// coalesced store.

#define HH 128
#define BB 8
#define LL 8192
#define NN 64

typedef unsigned long long u64;

__device__ __forceinline__ u64 pk2(float lo, float hi) {
    u64 r; asm("mov.b64 %0, {%1, %2};" : "=l"(r) : "f"(lo), "f"(hi)); return r;
}
__device__ __forceinline__ void upk2(u64 v, float& lo, float& hi) {
    asm("mov.b64 {%0, %1}, %2;" : "=f"(lo), "=f"(hi) : "l"(v));
}
__device__ __forceinline__ u64 fma2(u64 a, u64 b, u64 c) {
    u64 d; asm("fma.rn.f32x2 %0, %1, %2, %3;" : "=l"(d) : "l"(a), "l"(b), "l"(c)); return d;
}
__device__ __forceinline__ u64 mul2(u64 a, u64 b) {
    u64 d; asm("mul.rn.f32x2 %0, %1, %2;" : "=l"(d) : "l"(a), "l"(b)); return d;
}
__device__ __forceinline__ u64 add2(u64 a, u64 b) {
    u64 d; asm("add.rn.f32x2 %0, %1, %2;" : "=l"(d) : "l"(a), "l"(b)); return d;
}

__global__ void __launch_bounds__(32) s4d_scan_kernel(
    const float* __restrict__ x,      // (B,H,L)
    const float* __restrict__ Are,    // (H,N,1)
    const float* __restrict__ Aim,    // (H,N,1)
    const float* __restrict__ Cm,     // (H,N,2)
    const float* __restrict__ Dv,     // (1,H,1)
    const float* __restrict__ logdt,  // (H,1,1)
    float* __restrict__ out)          // (B,H,L)
{
    const int g    = blockIdx.x;        // g = b*H + h
    const int h    = g & (HH - 1);
    const int lane = threadIdx.x;

    // ---- per-mode parameter setup in double (errors in w compound over the
    //      8192-step horizon; one rounding to fp32 at the end) ----
    const double dt = exp((double)logdt[h]);
    float wrf[2], wif[2], w2rf[2], w2if[2], grf[2], gif[2], gwrf[2], gwif[2];
#pragma unroll
    for (int k = 0; k < 2; ++k) {
        const int idx = h * NN + lane + 32 * k;
        const double ar = fmin((double)Are[idx], -1e-4);
        const double ai = (double)Aim[idx];
        const double er = exp(dt * ar);
        double si, co; sincos(dt * ai, &si, &co);
        const double wr = er * co, wi = er * si;
        // cons = (w - 1)/A
        const double den = ar * ar + ai * ai;
        const double cr  = ((wr - 1.0) * ar + wi * ai) / den;
        const double ci  = (wi * ar - (wr - 1.0) * ai) / den;
        // g = Cc * cons
        const double Cre = (double)Cm[idx * 2 + 0];
        const double Cim = (double)Cm[idx * 2 + 1];
        const double gr  = Cre * cr - Cim * ci;
        const double gi  = Cre * ci + Cim * cr;
        wrf[k]  = (float)wr;                 wif[k]  = (float)wi;
        w2rf[k] = (float)(wr * wr - wi * wi); w2if[k] = (float)(2.0 * wr * wi);
        grf[k]  = (float)gr;                 gif[k]  = (float)gi;
        gwrf[k] = (float)(gr * wr - gi * wi); gwif[k] = (float)(gr * wi + gi * wr);
    }
    const u64 wrv   = pk2(wrf[0],   wrf[1]);
    const u64 wiv   = pk2(wif[0],   wif[1]);
    const u64 w2rv  = pk2(w2rf[0],  w2rf[1]);
    const u64 w2iv  = pk2(w2if[0],  w2if[1]);
    const u64 mw2iv = pk2(-w2if[0], -w2if[1]);
    const u64 grv   = pk2(grf[0],   grf[1]);
    const u64 mgiv  = pk2(-gif[0],  -gif[1]);
    const u64 gwrv  = pk2(gwrf[0],  gwrf[1]);
    const u64 mgwiv = pk2(-gwif[0], -gwif[1]);
    const float Dh  = Dv[h];

    const float* xrow = x   + (size_t)g * LL;
    float*       orow = out + (size_t)g * LL;

    // prefetch tile 0: xa = x[l0+lane] (for D term / store), xb = x[l0+1+lane]
    // (recurrence inputs)
    float xa = __ldg(xrow + lane);
    float xb = (lane < 31) ? __ldg(xrow + 1 + lane) : __ldg(xrow + 32);

    // z = s[0] = x[0]  (invariant at tile top: z = s[l0])
    const float x0 = __shfl_sync(0xffffffffu, xa, 0);
    u64 zr = pk2(x0, x0);
    u64 zi = pk2(0.f, 0.f);

    for (int l0 = 0; l0 < LL; l0 += 32) {
        float xa_n = 0.f, xb_n = 0.f;
        if (l0 + 32 < LL) {
            xa_n = __ldg(xrow + l0 + 32 + lane);
            const int ib = l0 + 33 + lane;
            xb_n = (ib < LL) ? __ldg(xrow + ib) : 0.f;
        }

        u64 part[32];
#pragma unroll
        for (int j = 0; j < 16; ++j) {
            const float x1 = __shfl_sync(0xffffffffu, xb, 2 * j);
            const float x2 = __shfl_sync(0xffffffffu, xb, 2 * j + 1);
            const u64 x1p = pk2(x1, x1);
            const u64 x2p = pk2(x2, x2);

            // outputs from held state z = s[l0+2j]  (independent of the chain)
            u64 pd  = mul2(grv, zr);           // y_even: Re(g z)
            pd      = fma2(mgiv, zi, pd);
            u64 pd2 = mul2(gwrv, zr);          // y_odd: Re(gw z) + Re(g) x1
            pd2     = fma2(mgwiv, zi, pd2);
            pd2     = fma2(grv, x1p, pd2);
            part[2 * j]     = pd;
            part[2 * j + 1] = pd2;

            // state advance by 2: z <- w^2 z + (w x1 + x2)
            const u64 accr = fma2(wrv, x1p, x2p);
            const u64 acci = mul2(wiv, x1p);
            u64 nzr = fma2(w2rv, zr, accr);
            nzr     = fma2(mw2iv, zi, nzr);
            u64 nzi = fma2(w2iv, zr, acci);
            nzi     = fma2(w2rv, zi, nzi);
            zr = nzr; zi = nzi;
        }

        // ---- packed cross-lane transpose-fold: lane t ends with
        //      (sum over lanes of part_lo[t], sum over lanes of part_hi[t]) ----
#pragma unroll
        for (int o = 16; o >= 1; o >>= 1) {
            const bool hiHalf = (lane & o) != 0;
            u64 tmp[16];
#pragma unroll
            for (int t = 0; t < o; ++t) {
                const u64 a    = part[t];
                const u64 bq   = part[t + o];
                const u64 send = hiHalf ? a : bq;
                const u64 recv = __shfl_xor_sync(0xffffffffu, send, o);
                tmp[t] = add2(hiHalf ? bq : a, recv);
            }
#pragma unroll
            for (int t = 0; t < o; ++t) part[t] = tmp[t];
        }

        float plo, phi; upk2(part[0], plo, phi);
        orow[l0 + lane] = fmaf(Dh, xa, plo + phi);

        xa = xa_n; xb = xb_n;
    }
}

extern "C" void kernel_launch(void* const* d_in, const int* in_sizes, int n_in,
                              void* d_out, int out_size)
{
    const float* x     = (const float*)d_in[0];
    const float* Are   = (const float*)d_in[1];
    const float* Aim   = (const float*)d_in[2];
    const float* Cm    = (const float*)d_in[3];
    const float* Dv    = (const float*)d_in[4];
    const float* logdt = (const float*)d_in[5];
    float* out = (float*)d_out;

    s4d_scan_kernel<<<BB * HH, 32>>>(x, Are, Aim, Cm, Dv, logdt, out);
}